// round 2
// baseline (speedup 1.0000x reference)
#include <cuda_runtime.h>
#include <math.h>

// VAE_RNN: B=4096, T=200, D=128, L=64, H=128, cin=2L+D=256.
// Persistent kernel: 128 CTAs x 256 threads; each CTA owns 32 batch rows for
// all 200 steps. State (y,s), second-layer weights, activations in SMEM.
// First-layer weights streamed from L2 each step. Inner loops use Blackwell
// packed fma.rn.f32x2 (2 fp32 FMAs/issue) paired along the N dimension.

#define NB 4096
#define NT 200
#define ND 128
#define NL 64
#define NH 128
#define M_ROWS 32
#define THREADS 256
#define NBLOCKS (NB / M_ROWS)   // 128

// ---- shared memory layout (float offsets) ----
#define OFF_W2CAT 0           // [128][128]  (ug_w2 | rg_w2)   16384
#define OFF_WNS2  16384       // [128][128]  ns_w2             16384
#define OFF_G1T   32768       // [256][32]   G1^T (also G2^T)   8192
#define OFF_XT    40960       // [128][32]   x^T                4096
#define OFF_HCT   45056       // [128][32]   hc^T (y*r | s*r)   4096
#define OFF_YT    49152       // [64][32]    y^T                2048
#define OFF_ST    51200       // [64][32]    s^T                2048
#define OFF_UT    53248       // [64][32]    u^T                2048
#define OFF_RT    55296       // [64][32]    r^T                2048
#define OFF_B1C   57344       // [256] (ug_b1 | rg_b1)
#define OFF_B2C   57600       // [128] (ug_b2 | rg_b2)
#define OFF_BN1   57728       // [128] ns_b1
#define OFF_BN2   57856       // [128] ns_b2
#define SMEM_FLOATS 57984     // 231,936 bytes (< 232,448 opt-in limit)

typedef unsigned long long u64;

__device__ __forceinline__ u64 dup2(float x) {
    u64 r; unsigned xi = __float_as_uint(x);
    asm("mov.b64 %0, {%1, %1};" : "=l"(r) : "r"(xi));
    return r;
}
__device__ __forceinline__ void fma2(u64& c, u64 a, u64 b) {
    asm("fma.rn.f32x2 %0, %1, %2, %0;" : "+l"(c) : "l"(a), "l"(b));
}
__device__ __forceinline__ float2 unpk(u64 v) {
    unsigned lo, hi;
    asm("mov.b64 {%0, %1}, %2;" : "=r"(lo), "=r"(hi) : "l"(v));
    return make_float2(__uint_as_float(lo), __uint_as_float(hi));
}

__device__ __forceinline__ float fast_tanhf(float x) {
    float ax = fabsf(x);
    float e  = __expf(-2.0f * ax);
    float t  = __fdividef(1.0f - e, 1.0f + e);
    return copysignf(t, x);
}
__device__ __forceinline__ float fast_sigmoidf(float x) {
    return __fdividef(1.0f, 1.0f + __expf(-x));
}

__global__ void __launch_bounds__(THREADS, 1) vae_rnn_kernel(
    const float* __restrict__ data,
    const float* __restrict__ ug_w1, const float* __restrict__ ug_b1,
    const float* __restrict__ ug_w2, const float* __restrict__ ug_b2,
    const float* __restrict__ rg_w1, const float* __restrict__ rg_b1,
    const float* __restrict__ rg_w2, const float* __restrict__ rg_b2,
    const float* __restrict__ ns_w1, const float* __restrict__ ns_b1,
    const float* __restrict__ ns_w2, const float* __restrict__ ns_b2,
    float* __restrict__ out)
{
    extern __shared__ float sm[];
    float* W2cat = sm + OFF_W2CAT;
    float* Wns2  = sm + OFF_WNS2;
    float* g1T   = sm + OFF_G1T;
    float* xT    = sm + OFF_XT;
    float* hcT   = sm + OFF_HCT;
    float* yT    = sm + OFF_YT;
    float* sT    = sm + OFF_ST;
    float* uT    = sm + OFF_UT;
    float* rT    = sm + OFF_RT;
    float* b1c   = sm + OFF_B1C;
    float* b2c   = sm + OFF_B2C;
    float* bn1   = sm + OFF_BN1;
    float* bn2   = sm + OFF_BN2;

    const int tid = threadIdx.x;
    const int b0  = blockIdx.x * M_ROWS;

    // ---- one-time init: resident weights, biases, zero state ----
    for (int i = tid; i < 128 * 128; i += THREADS) {
        int k = i >> 7, n = i & 127;
        W2cat[i] = (n < 64) ? ug_w2[k * 64 + n] : rg_w2[k * 64 + (n - 64)];
        Wns2[i]  = ns_w2[i];
    }
    for (int i = tid; i < 256; i += THREADS)
        b1c[i] = (i < 128) ? ug_b1[i] : rg_b1[i - 128];
    if (tid < 128) {
        b2c[tid] = (tid < 64) ? ug_b2[tid] : rg_b2[tid - 64];
        bn1[tid] = ns_b1[tid];
        bn2[tid] = ns_b2[tid];
    }
    for (int i = tid; i < NL * M_ROWS; i += THREADS) { yT[i] = 0.0f; sT[i] = 0.0f; }
    __syncthreads();

    // thread tiling: mg = row group (4 rows), ng = col group
    const int mg = tid & 7;        // rows mg*4 .. mg*4+3
    const int ng = tid >> 3;       // 0..31

    // GEMM1: cols ng*8..+8 of [ug|rg] first layer
    const float* w1ptr = (ng < 16) ? (ug_w1 + ng * 8) : (rg_w1 + (ng - 16) * 8);
    // GEMM3: cols ng*4..+4 of ns first layer
    const float* w3ptr = ns_w1 + ng * 4;

    const float4* yT4  = (const float4*)yT;
    const float4* sT4  = (const float4*)sT;
    const float4* xT4  = (const float4*)xT;
    const float4* hcT4 = (const float4*)hcT;
    const float4* g1T4c = (const float4*)g1T;
    float4*       g1T4  = (float4*)g1T;
    const ulonglong2* W2c64 = (const ulonglong2*)W2cat;
    const ulonglong2* Wn264 = (const ulonglong2*)Wns2;

    const float* xbase = data + (size_t)b0 * NT * ND;
    const int xm  = tid & 31;      // batch row within tile
    const int xdg = tid >> 5;      // d-group: d = xdg*16 .. +16

    for (int t = 0; t < NT; ++t) {
        // ---- load x tile transposed: xT[d][m] ----
        {
            const float4* src = (const float4*)(xbase + (size_t)xm * (NT * ND) + t * ND + xdg * 16);
            float4 v0 = __ldg(src + 0);
            float4 v1 = __ldg(src + 1);
            float4 v2 = __ldg(src + 2);
            float4 v3 = __ldg(src + 3);
            float vals[16] = { v0.x, v0.y, v0.z, v0.w, v1.x, v1.y, v1.z, v1.w,
                               v2.x, v2.y, v2.z, v2.w, v3.x, v3.y, v3.z, v3.w };
            int base = (xdg * 16) * 32 + xm;
            #pragma unroll
            for (int j = 0; j < 16; ++j) xT[base + j * 32] = vals[j];
        }
        __syncthreads();

        // ---- GEMM1: G1[32x256] = tanh(h @ [ug_w1|rg_w1] + b1c), h=[y|s|x] ----
        {
            u64 acc[4][4];   // [m][n-pair], pairs along N
            #pragma unroll
            for (int i = 0; i < 4; ++i)
                #pragma unroll
                for (int j = 0; j < 4; ++j) acc[i][j] = 0ull;

            #pragma unroll 8
            for (int k = 0; k < 64; ++k) {
                float4 a = yT4[k * 8 + mg];
                u64 ad0 = dup2(a.x), ad1 = dup2(a.y), ad2 = dup2(a.z), ad3 = dup2(a.w);
                const ulonglong2* wr = (const ulonglong2*)(w1ptr + (size_t)k * 128);
                ulonglong2 wA = __ldg(wr);
                ulonglong2 wB = __ldg(wr + 1);
                fma2(acc[0][0], ad0, wA.x); fma2(acc[0][1], ad0, wA.y);
                fma2(acc[0][2], ad0, wB.x); fma2(acc[0][3], ad0, wB.y);
                fma2(acc[1][0], ad1, wA.x); fma2(acc[1][1], ad1, wA.y);
                fma2(acc[1][2], ad1, wB.x); fma2(acc[1][3], ad1, wB.y);
                fma2(acc[2][0], ad2, wA.x); fma2(acc[2][1], ad2, wA.y);
                fma2(acc[2][2], ad2, wB.x); fma2(acc[2][3], ad2, wB.y);
                fma2(acc[3][0], ad3, wA.x); fma2(acc[3][1], ad3, wA.y);
                fma2(acc[3][2], ad3, wB.x); fma2(acc[3][3], ad3, wB.y);
            }
            #pragma unroll 8
            for (int k = 0; k < 64; ++k) {
                float4 a = sT4[k * 8 + mg];
                u64 ad0 = dup2(a.x), ad1 = dup2(a.y), ad2 = dup2(a.z), ad3 = dup2(a.w);
                const ulonglong2* wr = (const ulonglong2*)(w1ptr + (size_t)(k + 64) * 128);
                ulonglong2 wA = __ldg(wr);
                ulonglong2 wB = __ldg(wr + 1);
                fma2(acc[0][0], ad0, wA.x); fma2(acc[0][1], ad0, wA.y);
                fma2(acc[0][2], ad0, wB.x); fma2(acc[0][3], ad0, wB.y);
                fma2(acc[1][0], ad1, wA.x); fma2(acc[1][1], ad1, wA.y);
                fma2(acc[1][2], ad1, wB.x); fma2(acc[1][3], ad1, wB.y);
                fma2(acc[2][0], ad2, wA.x); fma2(acc[2][1], ad2, wA.y);
                fma2(acc[2][2], ad2, wB.x); fma2(acc[2][3], ad2, wB.y);
                fma2(acc[3][0], ad3, wA.x); fma2(acc[3][1], ad3, wA.y);
                fma2(acc[3][2], ad3, wB.x); fma2(acc[3][3], ad3, wB.y);
            }
            #pragma unroll 8
            for (int k = 0; k < 128; ++k) {
                float4 a = xT4[k * 8 + mg];
                u64 ad0 = dup2(a.x), ad1 = dup2(a.y), ad2 = dup2(a.z), ad3 = dup2(a.w);
                const ulonglong2* wr = (const ulonglong2*)(w1ptr + (size_t)(k + 128) * 128);
                ulonglong2 wA = __ldg(wr);
                ulonglong2 wB = __ldg(wr + 1);
                fma2(acc[0][0], ad0, wA.x); fma2(acc[0][1], ad0, wA.y);
                fma2(acc[0][2], ad0, wB.x); fma2(acc[0][3], ad0, wB.y);
                fma2(acc[1][0], ad1, wA.x); fma2(acc[1][1], ad1, wA.y);
                fma2(acc[1][2], ad1, wB.x); fma2(acc[1][3], ad1, wB.y);
                fma2(acc[2][0], ad2, wA.x); fma2(acc[2][1], ad2, wA.y);
                fma2(acc[2][2], ad2, wB.x); fma2(acc[2][3], ad2, wB.y);
                fma2(acc[3][0], ad3, wA.x); fma2(acc[3][1], ad3, wA.y);
                fma2(acc[3][2], ad3, wB.x); fma2(acc[3][3], ad3, wB.y);
            }
            // bias + tanh + store transposed g1T[col][m]
            #pragma unroll
            for (int j = 0; j < 4; ++j) {
                int colA = ng * 8 + 2 * j;
                float bA = b1c[colA], bB = b1c[colA + 1];
                float2 p0 = unpk(acc[0][j]), p1 = unpk(acc[1][j]);
                float2 p2 = unpk(acc[2][j]), p3 = unpk(acc[3][j]);
                float4 vA = make_float4(fast_tanhf(p0.x + bA), fast_tanhf(p1.x + bA),
                                        fast_tanhf(p2.x + bA), fast_tanhf(p3.x + bA));
                float4 vB = make_float4(fast_tanhf(p0.y + bB), fast_tanhf(p1.y + bB),
                                        fast_tanhf(p2.y + bB), fast_tanhf(p3.y + bB));
                g1T4[colA * 8 + mg] = vA;
                g1T4[(colA + 1) * 8 + mg] = vB;
            }
        }
        __syncthreads();

        // ---- GEMM2: [u_pre | r_pre][32x128]; u from G1[:, :128], r from G1[:,128:] ----
        {
            u64 d[4][2];
            #pragma unroll
            for (int i = 0; i < 4; ++i) { d[i][0] = 0ull; d[i][1] = 0ull; }
            const float4* aB = g1T4c + ((ng < 16) ? 0 : 128 * 8);
            #pragma unroll 8
            for (int k = 0; k < 128; ++k) {
                float4 a = aB[k * 8 + mg];
                u64 ad0 = dup2(a.x), ad1 = dup2(a.y), ad2 = dup2(a.z), ad3 = dup2(a.w);
                ulonglong2 w = W2c64[k * 32 + ng];
                fma2(d[0][0], ad0, w.x); fma2(d[0][1], ad0, w.y);
                fma2(d[1][0], ad1, w.x); fma2(d[1][1], ad1, w.y);
                fma2(d[2][0], ad2, w.x); fma2(d[2][1], ad2, w.y);
                fma2(d[3][0], ad3, w.x); fma2(d[3][1], ad3, w.y);
            }
            int n0 = ng * 4;
            float* dst = (ng < 16) ? (uT + n0 * 32) : (rT + (n0 - 64) * 32);
            #pragma unroll
            for (int j = 0; j < 2; ++j) {
                float bA = b2c[n0 + 2 * j], bB = b2c[n0 + 2 * j + 1];
                float2 q0 = unpk(d[0][j]), q1 = unpk(d[1][j]);
                float2 q2 = unpk(d[2][j]), q3 = unpk(d[3][j]);
                float* pA = dst + (2 * j) * 32 + mg * 4;
                pA[0] = fast_sigmoidf(q0.x + bA); pA[1] = fast_sigmoidf(q1.x + bA);
                pA[2] = fast_sigmoidf(q2.x + bA); pA[3] = fast_sigmoidf(q3.x + bA);
                float* pB = dst + (2 * j + 1) * 32 + mg * 4;
                pB[0] = fast_sigmoidf(q0.y + bB); pB[1] = fast_sigmoidf(q1.y + bB);
                pB[2] = fast_sigmoidf(q2.y + bB); pB[3] = fast_sigmoidf(q3.y + bB);
            }
        }
        __syncthreads();

        // ---- build hcT = [y*r | s*r] (x part reused from xT) ----
        #pragma unroll
        for (int i = 0; i < 16; ++i) {
            int flat = tid + i * THREADS;       // 0..4095 = k*32+m
            int k = flat >> 5, m = flat & 31;
            float r = rT[(k & 63) * 32 + m];
            float v = (k < 64) ? yT[k * 32 + m] : sT[(k - 64) * 32 + m];
            hcT[flat] = v * r;
        }
        __syncthreads();

        // ---- GEMM3: G2[32x128] = tanh(hc @ ns_w1 + bn1) ----
        {
            u64 e[4][2];
            #pragma unroll
            for (int i = 0; i < 4; ++i) { e[i][0] = 0ull; e[i][1] = 0ull; }
            #pragma unroll 8
            for (int k = 0; k < 128; ++k) {
                float4 a = hcT4[k * 8 + mg];
                u64 ad0 = dup2(a.x), ad1 = dup2(a.y), ad2 = dup2(a.z), ad3 = dup2(a.w);
                ulonglong2 w = __ldg((const ulonglong2*)(w3ptr + (size_t)k * 128));
                fma2(e[0][0], ad0, w.x); fma2(e[0][1], ad0, w.y);
                fma2(e[1][0], ad1, w.x); fma2(e[1][1], ad1, w.y);
                fma2(e[2][0], ad2, w.x); fma2(e[2][1], ad2, w.y);
                fma2(e[3][0], ad3, w.x); fma2(e[3][1], ad3, w.y);
            }
            #pragma unroll 8
            for (int k = 0; k < 128; ++k) {
                float4 a = xT4[k * 8 + mg];
                u64 ad0 = dup2(a.x), ad1 = dup2(a.y), ad2 = dup2(a.z), ad3 = dup2(a.w);
                ulonglong2 w = __ldg((const ulonglong2*)(w3ptr + (size_t)(k + 128) * 128));
                fma2(e[0][0], ad0, w.x); fma2(e[0][1], ad0, w.y);
                fma2(e[1][0], ad1, w.x); fma2(e[1][1], ad1, w.y);
                fma2(e[2][0], ad2, w.x); fma2(e[2][1], ad2, w.y);
                fma2(e[3][0], ad3, w.x); fma2(e[3][1], ad3, w.y);
            }
            int n0 = ng * 4;
            #pragma unroll
            for (int j = 0; j < 2; ++j) {
                int colA = n0 + 2 * j;
                float bA = bn1[colA], bB = bn1[colA + 1];
                float2 p0 = unpk(e[0][j]), p1 = unpk(e[1][j]);
                float2 p2 = unpk(e[2][j]), p3 = unpk(e[3][j]);
                float4 vA = make_float4(fast_tanhf(p0.x + bA), fast_tanhf(p1.x + bA),
                                        fast_tanhf(p2.x + bA), fast_tanhf(p3.x + bA));
                float4 vB = make_float4(fast_tanhf(p0.y + bB), fast_tanhf(p1.y + bB),
                                        fast_tanhf(p2.y + bB), fast_tanhf(p3.y + bB));
                g1T4[colA * 8 + mg] = vA;        // reuse g1T as G2^T [128][32]
                g1T4[(colA + 1) * 8 + mg] = vB;
            }
        }
        __syncthreads();

        // ---- GEMM4: ns[32x128] = G2 @ ns_w2 + bn2; gated state update ----
        {
            u64 f[4][2];
            #pragma unroll
            for (int i = 0; i < 4; ++i) { f[i][0] = 0ull; f[i][1] = 0ull; }
            #pragma unroll 8
            for (int k = 0; k < 128; ++k) {
                float4 a = g1T4c[k * 8 + mg];
                u64 ad0 = dup2(a.x), ad1 = dup2(a.y), ad2 = dup2(a.z), ad3 = dup2(a.w);
                ulonglong2 w = Wn264[k * 32 + ng];
                fma2(f[0][0], ad0, w.x); fma2(f[0][1], ad0, w.y);
                fma2(f[1][0], ad1, w.x); fma2(f[1][1], ad1, w.y);
                fma2(f[2][0], ad2, w.x); fma2(f[2][1], ad2, w.y);
                fma2(f[3][0], ad3, w.x); fma2(f[3][1], ad3, w.y);
            }
            int n0 = ng * 4;
            #pragma unroll
            for (int j = 0; j < 2; ++j) {
                float2 q[4] = { unpk(f[0][j]), unpk(f[1][j]), unpk(f[2][j]), unpk(f[3][j]) };
                #pragma unroll
                for (int half = 0; half < 2; ++half) {
                    int n = n0 + 2 * j + half;
                    int l = n & 63;
                    float bb = bn2[n];
                    float* st = (n < 64) ? yT : sT;
                    #pragma unroll
                    for (int i = 0; i < 4; ++i) {
                        int m = mg * 4 + i;
                        float raw = (half == 0 ? q[i].x : q[i].y) + bb;
                        float nv  = (n < 64) ? raw : fabsf(raw);
                        float u   = uT[l * 32 + m];
                        float old = st[l * 32 + m];
                        st[l * 32 + m] = (1.0f - u) * nv + u * old;
                    }
                }
            }
        }
        __syncthreads();
    }

    // ---- write output: y (4096x64) then s (4096x64), row-major ----
    for (int i = tid; i < M_ROWS * NL; i += THREADS) {
        int m = i >> 6, l = i & 63;
        out[(size_t)(b0 + m) * NL + l] = yT[l * 32 + m];
        out[(size_t)NB * NL + (size_t)(b0 + m) * NL + l] = sT[l * 32 + m];
    }
}

extern "C" void kernel_launch(void* const* d_in, const int* in_sizes, int n_in,
                              void* d_out, int out_size) {
    const float* data  = (const float*)d_in[0];
    // d_in[1] = time_steps (unused by the reference)
    const float* ug_w1 = (const float*)d_in[2];
    const float* ug_b1 = (const float*)d_in[3];
    const float* ug_w2 = (const float*)d_in[4];
    const float* ug_b2 = (const float*)d_in[5];
    const float* rg_w1 = (const float*)d_in[6];
    const float* rg_b1 = (const float*)d_in[7];
    const float* rg_w2 = (const float*)d_in[8];
    const float* rg_b2 = (const float*)d_in[9];
    const float* ns_w1 = (const float*)d_in[10];
    const float* ns_b1 = (const float*)d_in[11];
    const float* ns_w2 = (const float*)d_in[12];
    const float* ns_b2 = (const float*)d_in[13];
    float* out = (float*)d_out;

    size_t smem_bytes = (size_t)SMEM_FLOATS * sizeof(float);
    cudaFuncSetAttribute(vae_rnn_kernel,
                         cudaFuncAttributeMaxDynamicSharedMemorySize,
                         (int)smem_bytes);
    vae_rnn_kernel<<<NBLOCKS, THREADS, smem_bytes>>>(
        data,
        ug_w1, ug_b1, ug_w2, ug_b2,
        rg_w1, rg_b1, rg_w2, rg_b2,
        ns_w1, ns_b1, ns_w2, ns_b2,
        out);
}